// round 4
// baseline (speedup 1.0000x reference)
#include <cuda_runtime.h>
#include <cuda_bf16.h>
#include <cstdint>

// BoxCrop: crop -> aspect-preserving bilinear resize (long side = 336) -> pad(127)
// images: [64, 3, 768, 768] f32, boxes: [64, 4] i32 (XYWH), out: [64, 3, 336, 336] f32
// 4 output pixels per thread along x; float4 stores; y-side math amortized;
// register-trimmed + forced 6 blocks/SM for occupancy.
// NOTE: x1/y1 must be clamped from the UNCLAMPED floor index (JAX semantics).

#define O_SIZE   336
#define IMG_H    768
#define IMG_W    768
#define FILL_V   127.0f
#define GROUPS_X 84          // 336 / 4

__global__ void __launch_bounds__(256, 6) boxcrop_kernel(
    const float* __restrict__ images,
    const int* __restrict__ boxes,
    float* __restrict__ out)
{
    const int b  = blockIdx.z;
    const int g  = blockIdx.x * blockDim.x + threadIdx.x;   // x-group index
    const int oy = blockIdx.y * blockDim.y + threadIdx.y;
    if (g >= GROUPS_X || oy >= O_SIZE) return;
    const int ox0 = g * 4;

    const int4 box = __ldg((const int4*)boxes + b);
    const int xb = box.x, yb = box.y, wb = box.z, hb = box.w;
    const float wf = (float)wb;
    const float hf = (float)hb;

    // Match JAX fp32 math: scale = 336/max; new_* = round-half-even(wf*scale)
    const float scale = 336.0f / fmaxf(wf, hf);
    const int new_w = (int)rintf(wf * scale);
    const int new_h = (int)rintf(hf * scale);
    const int pad_top  = (hb <  wb) ? (O_SIZE - new_h) / 2 : 0;
    const int pad_left = (hb >= wb) ? (O_SIZE - new_w) / 2 : 0;

    float4* outp = (float4*)(out + ((size_t)b * 3) * (O_SIZE * O_SIZE) + oy * O_SIZE + ox0);
    const int cstride4 = (O_SIZE * O_SIZE) / 4;   // float4 stride between channels

    const int iy  = oy  - pad_top;
    const int ix0 = ox0 - pad_left;

    const float4 fill4 = make_float4(FILL_V, FILL_V, FILL_V, FILL_V);

    // whole group out of the valid region -> pure fill, no loads
    if ((unsigned)iy >= (unsigned)new_h || ix0 + 3 < 0 || ix0 >= new_w) {
        outp[0]            = fill4;
        outp[cstride4]     = fill4;
        outp[2 * cstride4] = fill4;
        return;
    }

    // ---- y side (once per thread) ----
    const float src_y = (float)yb + (((float)iy + 0.5f) * hf) / (float)new_h - 0.5f;
    const float y0f = floorf(src_y);
    const float wy  = src_y - y0f;
    const int ylo = yb, yhi = yb + hb - 1;
    const int y0i = (int)y0f;
    const int y0 = min(max(y0i,     ylo), yhi);
    const int y1 = min(max(y0i + 1, ylo), yhi);
    const int r0 = y0 * IMG_W;
    const int r1 = y1 * IMG_W;
    const float owy = 1.0f - wy;

    // ---- x side (per pixel, indices reused across 3 channels) ----
    int   xi0[4], xi1[4];
    float wxv[4];
    const int xlo = xb, xhi = xb + wb - 1;
    const float new_wf = (float)new_w;
    #pragma unroll
    for (int j = 0; j < 4; j++) {
        const int ix = ix0 + j;
        const float src_x = (float)xb + (((float)ix + 0.5f) * wf) / new_wf - 0.5f;
        const float x0f = floorf(src_x);
        wxv[j] = src_x - x0f;
        const int x0i = (int)x0f;
        xi0[j] = min(max(x0i,     xlo), xhi);   // clamp from UNCLAMPED index
        xi1[j] = min(max(x0i + 1, xlo), xhi);   // clamp from UNCLAMPED index
    }

    const float* img = images + (size_t)b * 3 * (IMG_H * IMG_W);

    #pragma unroll
    for (int c = 0; c < 3; c++) {
        const float* p = img + (size_t)c * (IMG_H * IMG_W);
        float r[4];
        #pragma unroll
        for (int j = 0; j < 4; j++) {
            const float v00 = __ldg(p + r0 + xi0[j]);
            const float v01 = __ldg(p + r0 + xi1[j]);
            const float v10 = __ldg(p + r1 + xi0[j]);
            const float v11 = __ldg(p + r1 + xi1[j]);
            const float wx  = wxv[j];
            const float owx = 1.0f - wx;
            const float top = v00 * owx + v01 * wx;
            const float bot = v10 * owx + v11 * wx;
            const float val = top * owy + bot * wy;
            // validity recomputed (no stored array): ix in [0, new_w)
            r[j] = ((unsigned)(ix0 + j) < (unsigned)new_w) ? val : FILL_V;
        }
        outp[c * cstride4] = make_float4(r[0], r[1], r[2], r[3]);
    }
}

extern "C" void kernel_launch(void* const* d_in, const int* in_sizes, int n_in,
                              void* d_out, int out_size)
{
    const float* images = (const float*)d_in[0];
    const int*   boxes  = (const int*)d_in[1];
    float*       out    = (float*)d_out;

    dim3 block(32, 8, 1);
    dim3 grid((GROUPS_X + 31) / 32, (O_SIZE + 7) / 8, 64);
    boxcrop_kernel<<<grid, block>>>(images, boxes, out);
}

// round 6
// speedup vs baseline: 1.2168x; 1.2168x over previous
#include <cuda_runtime.h>
#include <cuda_bf16.h>
#include <cstdint>

// BoxCrop: crop -> aspect-preserving bilinear resize (long side = 336) -> pad(127)
// images: [64, 3, 768, 768] f32, boxes: [64, 4] i32 (XYWH), out: [64, 3, 336, 336] f32
// 4 output pixels per thread; ALL 48 gather loads batched for max MLP; float4 stores.

#define O_SIZE   336
#define IMG_H    768
#define IMG_W    768
#define IMG_HW   (IMG_H * IMG_W)
#define FILL_V   127.0f
#define GROUPS_X 84          // 336 / 4

__global__ void __launch_bounds__(256) boxcrop_kernel(
    const float* __restrict__ images,
    const int* __restrict__ boxes,
    float* __restrict__ out)
{
    const int b  = blockIdx.z;
    const int g  = blockIdx.x * blockDim.x + threadIdx.x;   // x-group index
    const int oy = blockIdx.y * blockDim.y + threadIdx.y;
    if (g >= GROUPS_X || oy >= O_SIZE) return;
    const int ox0 = g * 4;

    const int4 box = __ldg((const int4*)boxes + b);
    const int xb = box.x, yb = box.y, wb = box.z, hb = box.w;
    const float wf = (float)wb;
    const float hf = (float)hb;

    // Match JAX fp32 math: scale = 336/max; new_* = round-half-even(wf*scale)
    const float scale = 336.0f / fmaxf(wf, hf);
    const int new_w = (int)rintf(wf * scale);
    const int new_h = (int)rintf(hf * scale);
    const int pad_top  = (hb <  wb) ? (O_SIZE - new_h) / 2 : 0;
    const int pad_left = (hb >= wb) ? (O_SIZE - new_w) / 2 : 0;

    float4* outp = (float4*)(out + ((size_t)b * 3) * (O_SIZE * O_SIZE) + oy * O_SIZE + ox0);
    const int cstride4 = (O_SIZE * O_SIZE) / 4;

    const int iy  = oy  - pad_top;
    const int ix0 = ox0 - pad_left;

    const float4 fill4 = make_float4(FILL_V, FILL_V, FILL_V, FILL_V);

    // whole group outside the valid region -> pure fill, no loads
    if ((unsigned)iy >= (unsigned)new_h || ix0 + 3 < 0 || ix0 >= new_w) {
        outp[0]            = fill4;
        outp[cstride4]     = fill4;
        outp[2 * cstride4] = fill4;
        return;
    }

    // ---- y side (once per thread) ----
    const float src_y = (float)yb + (((float)iy + 0.5f) * hf) / (float)new_h - 0.5f;
    const float y0f = floorf(src_y);
    const float wy  = src_y - y0f;
    const int ylo = yb, yhi = yb + hb - 1;
    const int y0i = (int)y0f;
    const int y0 = min(max(y0i,     ylo), yhi);
    const int y1 = min(max(y0i + 1, ylo), yhi);
    const int r0 = y0 * IMG_W;
    const int r1 = y1 * IMG_W;
    const float owy = 1.0f - wy;

    // ---- x side (per pixel, clamp from UNCLAMPED floor index — JAX semantics) ----
    int   xi0[4], xi1[4];
    float wxv[4];
    const int xlo = xb, xhi = xb + wb - 1;
    const float new_wf = (float)new_w;
    #pragma unroll
    for (int j = 0; j < 4; j++) {
        const int ix = ix0 + j;
        const float src_x = (float)xb + (((float)ix + 0.5f) * wf) / new_wf - 0.5f;
        const float x0f = floorf(src_x);
        wxv[j] = src_x - x0f;
        const int x0i = (int)x0f;
        xi0[j] = min(max(x0i,     xlo), xhi);
        xi1[j] = min(max(x0i + 1, xlo), xhi);
    }

    const float* img = images + (size_t)b * 3 * IMG_HW;

    // ---- batch ALL 48 gather loads (3 channels x 4 px x 4 taps) for max MLP ----
    float v00[3][4], v01[3][4], v10[3][4], v11[3][4];
    #pragma unroll
    for (int c = 0; c < 3; c++) {
        const float* p = img + c * IMG_HW;
        #pragma unroll
        for (int j = 0; j < 4; j++) {
            v00[c][j] = __ldg(p + r0 + xi0[j]);
            v01[c][j] = __ldg(p + r0 + xi1[j]);
            v10[c][j] = __ldg(p + r1 + xi0[j]);
            v11[c][j] = __ldg(p + r1 + xi1[j]);
        }
    }

    // ---- blend + store ----
    #pragma unroll
    for (int c = 0; c < 3; c++) {
        float r[4];
        #pragma unroll
        for (int j = 0; j < 4; j++) {
            const float wx  = wxv[j];
            const float owx = 1.0f - wx;
            const float top = v00[c][j] * owx + v01[c][j] * wx;
            const float bot = v10[c][j] * owx + v11[c][j] * wx;
            const float val = top * owy + bot * wy;
            r[j] = ((unsigned)(ix0 + j) < (unsigned)new_w) ? val : FILL_V;
        }
        outp[c * cstride4] = make_float4(r[0], r[1], r[2], r[3]);
    }
}

extern "C" void kernel_launch(void* const* d_in, const int* in_sizes, int n_in,
                              void* d_out, int out_size)
{
    const float* images = (const float*)d_in[0];
    const int*   boxes  = (const int*)d_in[1];
    float*       out    = (float*)d_out;

    dim3 block(32, 8, 1);
    dim3 grid((GROUPS_X + 31) / 32, (O_SIZE + 7) / 8, 64);
    boxcrop_kernel<<<grid, block>>>(images, boxes, out);
}

// round 7
// speedup vs baseline: 1.3961x; 1.1473x over previous
#include <cuda_runtime.h>
#include <cuda_bf16.h>
#include <cstdint>

// BoxCrop: crop -> aspect-preserving bilinear resize (long side = 336) -> pad(127)
// images: [64, 3, 768, 768] f32, boxes: [64, 4] i32 (XYWH), out: [64, 3, 336, 336] f32
// 2 output pixels per thread; all 24 gather loads batched; float2 stores.
// Sweet spot between occupancy (reg budget) and per-thread MLP.

#define O_SIZE   336
#define IMG_H    768
#define IMG_W    768
#define IMG_HW   (IMG_H * IMG_W)
#define FILL_V   127.0f
#define GROUPS_X 168         // 336 / 2

__global__ void __launch_bounds__(256) boxcrop_kernel(
    const float* __restrict__ images,
    const int* __restrict__ boxes,
    float* __restrict__ out)
{
    const int b  = blockIdx.z;
    const int g  = blockIdx.x * blockDim.x + threadIdx.x;   // x-group index
    const int oy = blockIdx.y * blockDim.y + threadIdx.y;
    if (g >= GROUPS_X || oy >= O_SIZE) return;
    const int ox0 = g * 2;

    const int4 box = __ldg((const int4*)boxes + b);
    const int xb = box.x, yb = box.y, wb = box.z, hb = box.w;
    const float wf = (float)wb;
    const float hf = (float)hb;

    // Match JAX fp32 math: scale = 336/max; new_* = round-half-even(wf*scale)
    const float scale = 336.0f / fmaxf(wf, hf);
    const int new_w = (int)rintf(wf * scale);
    const int new_h = (int)rintf(hf * scale);
    const int pad_top  = (hb <  wb) ? (O_SIZE - new_h) / 2 : 0;
    const int pad_left = (hb >= wb) ? (O_SIZE - new_w) / 2 : 0;

    float2* outp = (float2*)(out + ((size_t)b * 3) * (O_SIZE * O_SIZE) + oy * O_SIZE + ox0);
    const int cstride2 = (O_SIZE * O_SIZE) / 2;

    const int iy  = oy  - pad_top;
    const int ix0 = ox0 - pad_left;

    const float2 fill2 = make_float2(FILL_V, FILL_V);

    // whole group outside the valid region -> pure fill, no loads
    if ((unsigned)iy >= (unsigned)new_h || ix0 + 1 < 0 || ix0 >= new_w) {
        outp[0]            = fill2;
        outp[cstride2]     = fill2;
        outp[2 * cstride2] = fill2;
        return;
    }

    // ---- y side (once per thread) ----
    const float src_y = (float)yb + (((float)iy + 0.5f) * hf) / (float)new_h - 0.5f;
    const float y0f = floorf(src_y);
    const float wy  = src_y - y0f;
    const int ylo = yb, yhi = yb + hb - 1;
    const int y0i = (int)y0f;
    const int y0 = min(max(y0i,     ylo), yhi);
    const int y1 = min(max(y0i + 1, ylo), yhi);
    const int r0 = y0 * IMG_W;
    const int r1 = y1 * IMG_W;
    const float owy = 1.0f - wy;

    // ---- x side (per pixel, clamp from UNCLAMPED floor index — JAX semantics) ----
    int   xi0[2], xi1[2];
    float wxv[2];
    const int xlo = xb, xhi = xb + wb - 1;
    const float new_wf = (float)new_w;
    #pragma unroll
    for (int j = 0; j < 2; j++) {
        const int ix = ix0 + j;
        const float src_x = (float)xb + (((float)ix + 0.5f) * wf) / new_wf - 0.5f;
        const float x0f = floorf(src_x);
        wxv[j] = src_x - x0f;
        const int x0i = (int)x0f;
        xi0[j] = min(max(x0i,     xlo), xhi);
        xi1[j] = min(max(x0i + 1, xlo), xhi);
    }

    const float* img = images + (size_t)b * 3 * IMG_HW;

    // ---- batch all 24 gather loads (3 channels x 2 px x 4 taps) for MLP ----
    float v00[3][2], v01[3][2], v10[3][2], v11[3][2];
    #pragma unroll
    for (int c = 0; c < 3; c++) {
        const float* p = img + c * IMG_HW;
        #pragma unroll
        for (int j = 0; j < 2; j++) {
            v00[c][j] = __ldg(p + r0 + xi0[j]);
            v01[c][j] = __ldg(p + r0 + xi1[j]);
            v10[c][j] = __ldg(p + r1 + xi0[j]);
            v11[c][j] = __ldg(p + r1 + xi1[j]);
        }
    }

    // ---- blend + store ----
    #pragma unroll
    for (int c = 0; c < 3; c++) {
        float r[2];
        #pragma unroll
        for (int j = 0; j < 2; j++) {
            const float wx  = wxv[j];
            const float owx = 1.0f - wx;
            const float top = v00[c][j] * owx + v01[c][j] * wx;
            const float bot = v10[c][j] * owx + v11[c][j] * wx;
            const float val = top * owy + bot * wy;
            r[j] = ((unsigned)(ix0 + j) < (unsigned)new_w) ? val : FILL_V;
        }
        outp[c * cstride2] = make_float2(r[0], r[1]);
    }
}

extern "C" void kernel_launch(void* const* d_in, const int* in_sizes, int n_in,
                              void* d_out, int out_size)
{
    const float* images = (const float*)d_in[0];
    const int*   boxes  = (const int*)d_in[1];
    float*       out    = (float*)d_out;

    dim3 block(32, 8, 1);
    dim3 grid((GROUPS_X + 31) / 32, (O_SIZE + 7) / 8, 64);
    boxcrop_kernel<<<grid, block>>>(images, boxes, out);
}